// round 17
// baseline (speedup 1.0000x reference)
#include <cuda_runtime.h>
#include <cuda_bf16.h>
#include <cstdint>

typedef uint32_t u32;
typedef uint64_t u64;
typedef unsigned short u16;

// ---------------------------------------------------------------------------
// MLSTMFixD round 17 = R16 (best, 3040us) + epi MLP fix:
//  - frac-filter: batch all 32 hist loads into regs (MLP 32), 4-way
//    accumulator tree (was serial load->fma chain at 32 regs)
//  - precombined bias sums g_bs1/g_bs2 (fewer loads per element)
//  - everything else byte-identical to R16
// ---------------------------------------------------------------------------

constexpr int T_   = 128;
constexpr int B_   = 256;
constexpr int I_   = 512;
constexpr int H_   = 512;
constexpr int O_   = 5;
constexpr int KLAG = 32;
constexpr int BH   = B_ * H_;
constexpr int N1   = 3 * H_;   // 1536
constexpr int N2   = 4 * H_;   // 2048

constexpr int SMEM_X = 3 * 65536;   // gemmx: 3 stages x 64KB
constexpr int SMEM_S = 2 * 32768;   // step gemms: 2 stages x 32KB

// ------------------------- device scratch (static) -------------------------
__device__ __align__(16) u16 g_xhi[T_ * B_ * I_], g_xlo[T_ * B_ * I_];
__device__ __align__(16) u16 g_WxHi[N1 * 512],  g_WxLo[N1 * 512];    // Wmih
__device__ __align__(16) u16 g_W1Hi[N1 * 512],  g_W1Lo[N1 * 512];    // Wmhh
__device__ __align__(16) u16 g_W2Hi[N2 * 1024], g_W2Lo[N2 * 1024];   // [Wih|Whh]
__device__ __align__(16) u16 g_h1hi[BH], g_h1lo[BH];
__device__ __align__(16) u16 g_h2hi[BH], g_h2lo[BH];
__device__ float g_c2[BH];
__device__ float g_sel[BH];
__device__ float g_hist[KLAG][BH];          // circular by (t & 31)
__device__ float g_wd[KLAG][H_];
__device__ float g_bs1[N1];                 // bmih + bmhh
__device__ float g_bs2[N2];                 // bih + bhh
__device__ float g_XW[(size_t)T_ * B_ * N1];  // x @ Wmih^T for all t (streamed)
__device__ float g_G1[2][B_ * N1];          // K-split partials
__device__ float g_G2[2][B_ * N2];

// ------------------------------- helpers ------------------------------------
__device__ __forceinline__ u32 smem_u32(const void* p) {
    u32 a;
    asm("{ .reg .u64 t; cvta.to.shared.u64 t, %1; cvt.u32.u64 %0, t; }" : "=r"(a) : "l"(p));
    return a;
}
__device__ __forceinline__ void cpasync16(u32 dst, const void* src) {
    asm volatile("cp.async.cg.shared.global [%0], [%1], 16;" :: "r"(dst), "l"(src));
}
#define CP_COMMIT() asm volatile("cp.async.commit_group;" ::: "memory")
#define CP_WAIT0()  asm volatile("cp.async.wait_group 0;" ::: "memory")
#define CP_WAIT1()  asm volatile("cp.async.wait_group 1;" ::: "memory")

#define LDSM4(r, addr) asm volatile(                                           \
    "ldmatrix.sync.aligned.m8n8.x4.shared.b16 {%0,%1,%2,%3}, [%4];"            \
    : "=r"((r)[0]), "=r"((r)[1]), "=r"((r)[2]), "=r"((r)[3]) : "r"(addr))

#define MMA(d, a, b0, b1) asm volatile(                                        \
    "mma.sync.aligned.m16n8k16.row.col.f32.bf16.bf16.f32 "                     \
    "{%0,%1,%2,%3}, {%4,%5,%6,%7}, {%8,%9}, {%0,%1,%2,%3};"                    \
    : "+f"((d)[0]), "+f"((d)[1]), "+f"((d)[2]), "+f"((d)[3])                   \
    : "r"((a)[0]), "r"((a)[1]), "r"((a)[2]), "r"((a)[3]), "r"(b0), "r"(b1))

__device__ __forceinline__ u16 bf16bits(__nv_bfloat16 v) {
    __nv_bfloat16_raw r = *reinterpret_cast<__nv_bfloat16_raw*>(&v);
    return r.x;
}
__device__ __forceinline__ void split1(float a, u16& h, u16& l) {
    __nv_bfloat16 bh = __float2bfloat16_rn(a);
    float r = a - __bfloat162float(bh);
    __nv_bfloat16 bl = __float2bfloat16_rn(r);
    h = bf16bits(bh);
    l = bf16bits(bl);
}
__device__ __forceinline__ void split4(float4 v, u32& h01, u32& h23, u32& l01, u32& l23) {
    u16 h0, l0, h1, l1, h2, l2, h3, l3;
    split1(v.x, h0, l0); split1(v.y, h1, l1);
    split1(v.z, h2, l2); split1(v.w, h3, l3);
    h01 = (u32)h0 | ((u32)h1 << 16);  h23 = (u32)h2 | ((u32)h3 << 16);
    l01 = (u32)l0 | ((u32)l1 << 16);  l23 = (u32)l2 | ((u32)l3 << 16);
}
__device__ __forceinline__ float sigf(float x) { return 1.0f / (1.0f + expf(-x)); }

// ------------------------------- init ---------------------------------------
__global__ __launch_bounds__(256) void init_kernel(
    const float* __restrict__ b_d,  const float* __restrict__ x,
    const float* __restrict__ Wmih, const float* __restrict__ Wmhh,
    const float* __restrict__ Wih,  const float* __restrict__ Whh,
    const float* __restrict__ bmih, const float* __restrict__ bmhh,
    const float* __restrict__ bih,  const float* __restrict__ bhh)
{
    const int tid = blockIdx.x * blockDim.x + threadIdx.x;
    const int tot = gridDim.x * blockDim.x;

    const int ngx = T_ * B_ * I_ / 4;
    for (int i = tid; i < ngx; i += tot) {
        float4 v = reinterpret_cast<const float4*>(x)[i];
        u32 h01, h23, l01, l23; split4(v, h01, h23, l01, l23);
        reinterpret_cast<uint2*>(g_xhi)[i] = make_uint2(h01, h23);
        reinterpret_cast<uint2*>(g_xlo)[i] = make_uint2(l01, l23);
    }

    const int ngWx = N1 * 512 / 4;
    for (int i = tid; i < ngWx; i += tot) {
        float4 v = reinterpret_cast<const float4*>(Wmih)[i];
        u32 h01, h23, l01, l23; split4(v, h01, h23, l01, l23);
        reinterpret_cast<uint2*>(g_WxHi)[i] = make_uint2(h01, h23);
        reinterpret_cast<uint2*>(g_WxLo)[i] = make_uint2(l01, l23);
    }
    for (int i = tid; i < ngWx; i += tot) {
        float4 v = reinterpret_cast<const float4*>(Wmhh)[i];
        u32 h01, h23, l01, l23; split4(v, h01, h23, l01, l23);
        reinterpret_cast<uint2*>(g_W1Hi)[i] = make_uint2(h01, h23);
        reinterpret_cast<uint2*>(g_W1Lo)[i] = make_uint2(l01, l23);
    }
    const int ngW2 = N2 * 1024 / 4;
    for (int i = tid; i < ngW2; i += tot) {
        int e = i * 4;
        int n = e >> 10, k = e & 1023;
        const float* src = (k < 512) ? (Wih + (size_t)n * 512 + k)
                                     : (Whh + (size_t)n * 512 + (k - 512));
        float4 v = *reinterpret_cast<const float4*>(src);
        u32 h01, h23, l01, l23; split4(v, h01, h23, l01, l23);
        reinterpret_cast<uint2*>(g_W2Hi)[i] = make_uint2(h01, h23);
        reinterpret_cast<uint2*>(g_W2Lo)[i] = make_uint2(l01, l23);
    }

    for (int i = tid; i < N1; i += tot) g_bs1[i] = bmih[i] + bmhh[i];
    for (int i = tid; i < N2; i += tot) g_bs2[i] = bih[i] + bhh[i];

    float4 z4 = make_float4(0.f, 0.f, 0.f, 0.f);
    for (int i = tid; i < KLAG * BH / 4; i += tot)
        reinterpret_cast<float4*>(&g_hist[0][0])[i] = z4;
    for (int i = tid; i < BH / 4; i += tot) {
        reinterpret_cast<float4*>(g_c2)[i]  = z4;
        reinterpret_cast<float4*>(g_sel)[i] = z4;
        reinterpret_cast<uint2*>(g_h1hi)[i] = make_uint2(0u, 0u);
        reinterpret_cast<uint2*>(g_h1lo)[i] = make_uint2(0u, 0u);
        reinterpret_cast<uint2*>(g_h2hi)[i] = make_uint2(0u, 0u);
        reinterpret_cast<uint2*>(g_h2lo)[i] = make_uint2(0u, 0u);
    }

    if (tid < H_) {
        float d = 0.5f * (1.0f / (1.0f + expf(-b_d[tid])));
        float c = 1.0f;
        for (int j = 1; j <= KLAG; j++) {
            c *= ((float)(j - 1) - d) / (float)j;
            g_wd[j - 1][tid] = c;
        }
    }
}

// ------------------- XW precompute (R13 throughput GEMM) ---------------------
__global__ __launch_bounds__(256, 1) void gemmx_kernel()
{
    extern __shared__ __align__(128) char smem[];
    const u32 sb  = smem_u32(smem);
    const int tid = threadIdx.x;
    const int wid = tid >> 5, lane = tid & 31;
    const int bn  = blockIdx.x * 128;
    const int bm  = blockIdx.y * 128;

    auto load_chunk = [&](int c, int stage) {
        const int k0 = c * 64;
        const u32 base = sb + stage * 65536;
#pragma unroll
        for (int it = 0; it < 4; it++) {
            const int u = tid + it * 256;
            const int r = u >> 3, cu = u & 7;
            const u32 so = (u32)(r * 128 + ((cu ^ (r & 7)) << 4));
            const size_t ao = (size_t)(bm + r) * 512 + k0 + cu * 8;
            const size_t bo = (size_t)(bn + r) * 512 + k0 + cu * 8;
            cpasync16(base + so,         g_xhi  + ao);
            cpasync16(base + 16384 + so, g_xlo  + ao);
            cpasync16(base + 32768 + so, g_WxHi + bo);
            cpasync16(base + 49152 + so, g_WxLo + bo);
        }
    };

    const int warp_m = wid & 1;
    const int warp_n = wid >> 1;
    const int arow0  = warp_m * 64 + (lane & 15);
    const int akh    = lane >> 4;
    const int asw    = arow0 & 7;
    const int brow0  = warp_n * 32 + (lane & 7) + ((lane >> 4) << 3);
    const int bkh    = (lane >> 3) & 1;
    const int bsw    = brow0 & 7;

    float acc[4][4][4] = {};

    load_chunk(0, 0); CP_COMMIT();
    load_chunk(1, 1); CP_COMMIT();

    for (int c = 0; c < 8; c++) {
        if (c + 1 < 8) { CP_WAIT1(); } else { CP_WAIT0(); }
        __syncthreads();
        if (c + 2 < 8) { load_chunk(c + 2, (c + 2) % 3); CP_COMMIT(); }

        const u32 Ah = sb + (c % 3) * 65536;
        const u32 Al = Ah + 16384;
        const u32 Bh = Ah + 32768;
        const u32 Bl = Ah + 49152;

#pragma unroll
        for (int kk = 0; kk < 4; kk++) {
            const u32 sa  = (((u32)(kk * 2 + akh) ^ (u32)asw) << 4);
            const u32 sbo = (((u32)(kk * 2 + bkh) ^ (u32)bsw) << 4);

            u32 ah[4][4], al[4][4], bh[2][4], bl[2][4];
#pragma unroll
            for (int mf = 0; mf < 4; mf++) {
                const u32 ro = (u32)((arow0 + mf * 16) * 128);
                LDSM4(ah[mf], Ah + ro + sa);
                LDSM4(al[mf], Al + ro + sa);
            }
#pragma unroll
            for (int bf = 0; bf < 2; bf++) {
                const u32 ro = (u32)((brow0 + bf * 16) * 128);
                LDSM4(bh[bf], Bh + ro + sbo);
                LDSM4(bl[bf], Bl + ro + sbo);
            }
#pragma unroll
            for (int mf = 0; mf < 4; mf++)
#pragma unroll
                for (int bf = 0; bf < 2; bf++)
#pragma unroll
                    for (int n8 = 0; n8 < 2; n8++) {
                        float* d = acc[mf][bf * 2 + n8];
                        MMA(d, ah[mf], bh[bf][2 * n8], bh[bf][2 * n8 + 1]);
                        MMA(d, ah[mf], bl[bf][2 * n8], bl[bf][2 * n8 + 1]);
                        MMA(d, al[mf], bh[bf][2 * n8], bh[bf][2 * n8 + 1]);
                    }
        }
    }

#pragma unroll
    for (int mf = 0; mf < 4; mf++)
#pragma unroll
        for (int j = 0; j < 4; j++) {
            const int gm = bm + warp_m * 64 + mf * 16 + (lane >> 2);
            const int gn = bn + warp_n * 32 + j * 8 + 2 * (lane & 3);
            __stcs(reinterpret_cast<float2*>(&g_XW[(size_t)gm * N1 + gn]),
                   make_float2(acc[mf][j][0], acc[mf][j][1]));
            __stcs(reinterpret_cast<float2*>(&g_XW[(size_t)(gm + 8) * N1 + gn]),
                   make_float2(acc[mf][j][2], acc[mf][j][3]));
        }
}

// ----------------- step GEMM body (R7, verbatim; device inline) --------------
template <int SET>
__device__ __forceinline__ void gemm_body(char* smem, int bnT, int bmT, int kz)
{
    constexpr int NC  = (SET == 1) ? 4 : 8;
    constexpr int ldB = (SET == 2) ? 1024 : 512;
    constexpr int ldG = (SET == 2) ? N2 : N1;

    const u32 sb  = smem_u32(smem);
    const int tid = threadIdx.x;
    const int wid = tid >> 5, lane = tid & 31;
    const int bn  = bnT * 64;
    const int bm  = bmT * 64;
    const int kbase = (SET == 1) ? kz * 256 : kz * 512;

    const u16* __restrict__ BHi = (SET == 1) ? g_W1Hi : g_W2Hi;
    const u16* __restrict__ BLo = (SET == 1) ? g_W1Lo : g_W2Lo;
    float* __restrict__ G = (SET == 1) ? g_G1[kz] : g_G2[kz];

    const int lr  = tid >> 3;
    const int lcu = tid & 7;
    auto load_chunk = [&](int c, int stage) {
        const int k0 = kbase + c * 64;
        const u16* ah; const u16* al; int kloc;
        if (SET == 2 && k0 >= 512) { ah = g_h2hi; al = g_h2lo; kloc = k0 - 512; }
        else                       { ah = g_h1hi; al = g_h1lo; kloc = k0;       }
        const u32 base = sb + stage * 32768;
#pragma unroll
        for (int j = 0; j < 2; j++) {
            const int r = lr + j * 32;
            const u32 so = (u32)(r * 128 + ((lcu ^ (r & 7)) << 4));
            const size_t ao = (size_t)(bm + r) * 512 + kloc + lcu * 8;
            const size_t bo = (size_t)(bn + r) * ldB + k0 + lcu * 8;
            cpasync16(base + so,         ah  + ao);
            cpasync16(base + 8192 + so,  al  + ao);
            cpasync16(base + 16384 + so, BHi + bo);
            cpasync16(base + 24576 + so, BLo + bo);
        }
    };

    const int warp_m = wid & 1;
    const int warp_n = wid >> 1;
    const int arow   = warp_m * 32 + (lane & 15);
    const int akh    = lane >> 4;
    const int asw    = arow & 7;
    const u32 aoff0  = (u32)(arow * 128);
    const u32 aoff1  = (u32)((arow + 16) * 128);
    const int brow   = warp_n * 16 + (lane & 7) + ((lane >> 4) << 3);
    const int bkh    = (lane >> 3) & 1;
    const int bsw    = brow & 7;
    const u32 boff   = (u32)(brow * 128);

    float acc[2][2][4] = {};

    load_chunk(0, 0); CP_COMMIT();
    for (int c = 0; c < NC; c++) {
        CP_WAIT0();
        __syncthreads();
        if (c + 1 < NC) { load_chunk(c + 1, (c + 1) & 1); CP_COMMIT(); }

        const u32 Ah = sb + (c & 1) * 32768;
        const u32 Al = Ah + 8192;
        const u32 Bh = Ah + 16384;
        const u32 Bl = Ah + 24576;
#pragma unroll
        for (int kk = 0; kk < 4; kk++) {
            const u32 sa  = (((u32)(kk * 2 + akh) ^ (u32)asw) << 4);
            const u32 sbo = (((u32)(kk * 2 + bkh) ^ (u32)bsw) << 4);
            u32 ah0[4], ah1[4], al0[4], al1[4], bh[4], bl[4];
            LDSM4(ah0, Ah + aoff0 + sa);
            LDSM4(ah1, Ah + aoff1 + sa);
            LDSM4(al0, Al + aoff0 + sa);
            LDSM4(al1, Al + aoff1 + sa);
            LDSM4(bh,  Bh + boff + sbo);
            LDSM4(bl,  Bl + boff + sbo);
#pragma unroll
            for (int nt = 0; nt < 2; nt++) {
                MMA(acc[0][nt], ah0, bh[2 * nt], bh[2 * nt + 1]);
                MMA(acc[1][nt], ah1, bh[2 * nt], bh[2 * nt + 1]);
                MMA(acc[0][nt], ah0, bl[2 * nt], bl[2 * nt + 1]);
                MMA(acc[1][nt], ah1, bl[2 * nt], bl[2 * nt + 1]);
                MMA(acc[0][nt], al0, bh[2 * nt], bh[2 * nt + 1]);
                MMA(acc[1][nt], al1, bh[2 * nt], bh[2 * nt + 1]);
            }
        }
    }

#pragma unroll
    for (int mt = 0; mt < 2; mt++)
#pragma unroll
        for (int nt = 0; nt < 2; nt++) {
            const int gm = bm + warp_m * 32 + mt * 16 + (lane >> 2);
            const int gn = bn + warp_n * 16 + nt * 8 + 2 * (lane & 3);
            *reinterpret_cast<float2*>(&G[(size_t)gm * ldG + gn]) =
                make_float2(acc[mt][nt][0], acc[mt][nt][1]);
            *reinterpret_cast<float2*>(&G[(size_t)(gm + 8) * ldG + gn]) =
                make_float2(acc[mt][nt][2], acc[mt][nt][3]);
        }
}

// standalone step GEMMs (prologue/tail)
template <int SET>
__global__ __launch_bounds__(256, 2) void gemm_kernel()
{
    extern __shared__ __align__(128) char smem[];
    gemm_body<SET>(smem, blockIdx.x, blockIdx.y, blockIdx.z);
}

// merged: blocks x<32 run g2(t) tile x; x>=32 run g1(t+1) tile x-32. 3 CTAs/SM.
__global__ __launch_bounds__(256, 3) void gemmstep_kernel()
{
    extern __shared__ __align__(128) char smem[];
    if (blockIdx.x < 32) gemm_body<2>(smem, blockIdx.x, blockIdx.y, blockIdx.z);
    else                 gemm_body<1>(smem, blockIdx.x - 32, blockIdx.y, blockIdx.z);
}

// --------------------- epi bodies (high-MLP rewrite) -------------------------
__device__ __forceinline__ void epi1_body(int idx, int t)
{
    const int b = idx >> 9, hc = idx & 511;
    const float* __restrict__ Ga = g_G1[0] + (size_t)b * N1;
    const float* __restrict__ Gb = g_G1[1] + (size_t)b * N1;
    const float* __restrict__ Gx = g_XW + ((size_t)t * B_ + b) * N1;

    // batch ALL loads first (independent addresses -> deep MLP)
    float hv[KLAG];
#pragma unroll
    for (int j = 1; j <= KLAG; j++)
        hv[j - 1] = g_hist[(t - j) & (KLAG - 1)][idx];

    float a0 = Ga[hc],        a1 = Ga[512 + hc],  a2 = Ga[1024 + hc];
    float b0 = Gb[hc],        b1 = Gb[512 + hc],  b2 = Gb[1024 + hc];
    float x0 = __ldcs(Gx + hc), x1 = __ldcs(Gx + 512 + hc), x2 = __ldcs(Gx + 1024 + hc);
    float s0 = g_bs1[hc],     s1 = g_bs1[512 + hc], s2 = g_bs1[1024 + hc];

    // 4-way accumulator tree over the 32-lag FIR
    float f0 = 0.f, f1 = 0.f, f2 = 0.f, f3 = 0.f;
#pragma unroll
    for (int j = 0; j < KLAG; j += 4) {
        f0 = fmaf(g_wd[j][hc],     hv[j],     f0);
        f1 = fmaf(g_wd[j + 1][hc], hv[j + 1], f1);
        f2 = fmaf(g_wd[j + 2][hc], hv[j + 2], f2);
        f3 = fmaf(g_wd[j + 3][hc], hv[j + 3], f3);
    }
    float fs = (f0 + f1) + (f2 + f3);

    float vi = sigf ((a0 + b0) + (x0 + s0));
    float vo = sigf ((a1 + b1) + (x1 + s1));
    float vg = tanhf((a2 + b2) + (x2 + s2));

    float c1 = vi * vg - fs;
    g_hist[t & (KLAG - 1)][idx] = c1;
    float h1n = vo * tanhf(c1);
    split1(h1n, g_h1hi[idx], g_h1lo[idx]);
}

__device__ __forceinline__ void epi2_body(
    int idx, const int* __restrict__ length, int t)
{
    const int b = idx >> 9, hc = idx & 511;
    const float* __restrict__ Ga = g_G2[0] + (size_t)b * N2;
    const float* __restrict__ Gb = g_G2[1] + (size_t)b * N2;

    float a0 = Ga[hc],        a1 = Ga[512 + hc];
    float a2 = Ga[1024 + hc], a3 = Ga[1536 + hc];
    float b0 = Gb[hc],        b1 = Gb[512 + hc];
    float b2 = Gb[1024 + hc], b3 = Gb[1536 + hc];
    float s0 = g_bs2[hc],     s1 = g_bs2[512 + hc];
    float s2 = g_bs2[1024 + hc], s3 = g_bs2[1536 + hc];
    float cp = g_c2[idx];
    int   lb = length[b];

    float xi = sigf ((a0 + b0) + s0);
    float xf = sigf ((a1 + b1) + s1);
    float xg = tanhf((a2 + b2) + s2);
    float xo = sigf ((a3 + b3) + s3);

    float cn = xf * cp + xi * xg;
    g_c2[idx] = cn;
    float hv = tanhf(xo * tanhf(cn));
    split1(hv, g_h2hi[idx], g_h2lo[idx]);
    if (lb == t) g_sel[idx] = hv;
}

__global__ __launch_bounds__(256) void epi1_kernel(int t)
{
    epi1_body(blockIdx.x * blockDim.x + threadIdx.x, t);
}
__global__ __launch_bounds__(256) void epi2_kernel(const int* __restrict__ length, int t)
{
    epi2_body(blockIdx.x * blockDim.x + threadIdx.x, length, t);
}
// fused: blocks [0,512) run epi1(t+1); blocks [512,1024) run epi2(t)
__global__ __launch_bounds__(256) void epiX_kernel(const int* __restrict__ length, int t)
{
    const int blk = blockIdx.x;
    if (blk < 512) {
        epi1_body(blk * blockDim.x + threadIdx.x, t + 1);
    } else {
        epi2_body((blk - 512) * blockDim.x + threadIdx.x, length, t);
    }
}

// ------------------------------- head ---------------------------------------
__global__ __launch_bounds__(128) void head_kernel(
    const float* __restrict__ Wout, const float* __restrict__ bout,
    float* __restrict__ out)
{
    const int warp = (blockIdx.x * blockDim.x + threadIdx.x) >> 5;
    const int lane = threadIdx.x & 31;
    if (warp >= B_) return;

    float p[O_] = {0.f, 0.f, 0.f, 0.f, 0.f};
    for (int h = lane; h < H_; h += 32) {
        float s = g_sel[warp * H_ + h];
#pragma unroll
        for (int o = 0; o < O_; o++) p[o] = fmaf(s, Wout[o * H_ + h], p[o]);
    }
#pragma unroll
    for (int o = 0; o < O_; o++)
#pragma unroll
        for (int off = 16; off > 0; off >>= 1)
            p[o] += __shfl_xor_sync(0xffffffffu, p[o], off);

    if (lane == 0) {
        float l[O_], m = -1e30f;
#pragma unroll
        for (int o = 0; o < O_; o++) { l[o] = p[o] + bout[o]; m = fmaxf(m, l[o]); }
        float s = 0.0f;
#pragma unroll
        for (int o = 0; o < O_; o++) s += expf(l[o] - m);
        float ls = logf(s);
#pragma unroll
        for (int o = 0; o < O_; o++) out[warp * O_ + o] = l[o] - m - ls;
    }
}

// ----------------------------- launcher -------------------------------------
extern "C" void kernel_launch(void* const* d_in, const int* in_sizes, int n_in,
                              void* d_out, int out_size)
{
    const float* x    = (const float*)d_in[0];
    const int*   len  = (const int*)  d_in[1];
    const float* b_d  = (const float*)d_in[2];
    const float* Wmih = (const float*)d_in[3];
    const float* Wmhh = (const float*)d_in[4];
    const float* bmih = (const float*)d_in[5];
    const float* bmhh = (const float*)d_in[6];
    const float* Wih  = (const float*)d_in[7];
    const float* Whh  = (const float*)d_in[8];
    const float* bih  = (const float*)d_in[9];
    const float* bhh  = (const float*)d_in[10];
    const float* Wout = (const float*)d_in[11];
    const float* bout = (const float*)d_in[12];
    float* out = (float*)d_out;

    cudaFuncSetAttribute(gemmx_kernel,    cudaFuncAttributeMaxDynamicSharedMemorySize, SMEM_X);
    cudaFuncSetAttribute(gemm_kernel<1>,  cudaFuncAttributeMaxDynamicSharedMemorySize, SMEM_S);
    cudaFuncSetAttribute(gemm_kernel<2>,  cudaFuncAttributeMaxDynamicSharedMemorySize, SMEM_S);
    cudaFuncSetAttribute(gemmstep_kernel, cudaFuncAttributeMaxDynamicSharedMemorySize, SMEM_S);

    init_kernel<<<1024, 256>>>(b_d, x, Wmih, Wmhh, Wih, Whh, bmih, bmhh, bih, bhh);

    // hoisted input projection over all timesteps (throughput GEMM)
    gemmx_kernel<<<dim3(N1 / 128, (T_ * B_) / 128), 256, SMEM_X>>>();

    // prologue: g1(0), epi1(0)
    gemm_kernel<1><<<dim3(N1 / 64, 4, 2), 256, SMEM_S>>>();
    epi1_kernel<<<BH / 256, 256>>>(0);

    // main loop: [g2(t) || g1(t+1)] -> [epi2(t) || epi1(t+1)]
    for (int t = 0; t < T_ - 1; t++) {
        gemmstep_kernel<<<dim3(32 + 24, 4, 2), 256, SMEM_S>>>();
        epiX_kernel<<<2 * (BH / 256), 256>>>(len, t);
    }

    // tail: g2(T-1), epi2(T-1)
    gemm_kernel<2><<<dim3(N2 / 64, 4, 2), 256, SMEM_S>>>();
    epi2_kernel<<<BH / 256, 256>>>(len, T_ - 1);

    head_kernel<<<64, 128>>>(Wout, bout, out);
}